// round 13
// baseline (speedup 1.0000x reference)
#include <cuda_runtime.h>
#include <cuda_bf16.h>
#include <math.h>
#include <stdint.h>

// ---------------- problem constants ----------------
#define BB 16384      // batch
#define FF 26         // onehot fields
#define EE 32         // embedding dim
#define LL 50         // bag length
#define D0 909
#define D1 512
#define D2 256
#define XS 928        // D0 padded (zero tail), multiple of 32

// ---------------- scratch (static device globals: allocation-free) ----------
__device__ __nv_bfloat16 g_X  [(size_t)BB * XS];   // activations bf16
__device__ __nv_bfloat16 g_W2p[(size_t)D1 * XS];   // padded w2 bf16
__device__ __nv_bfloat16 g_W3r[(size_t)D2 * D1];   // w3 bf16
__device__ __nv_bfloat16 g_H1 [(size_t)BB * D1];   // layer-1 out bf16
__device__ float         g_zp [(size_t)8 * BB];    // fused layer-3 partials [8][B]
__device__ float         g_wide[BB];

// ---------------- helpers ----------------------------------------------------
#define CP16(dst, src) \
    asm volatile("cp.async.cg.shared.global [%0], [%1], 16;\n" :: "r"(dst), "l"(src))
#define CPCOMMIT() asm volatile("cp.async.commit_group;\n" ::)
#define CPWAIT0()  asm volatile("cp.async.wait_group 0;\n" ::)
#define CPWAIT1()  asm volatile("cp.async.wait_group 1;\n" ::)

__device__ __forceinline__ void ldsm_x4(uint32_t* r, uint32_t addr) {
    asm volatile("ldmatrix.sync.aligned.m8n8.x4.shared.b16 {%0,%1,%2,%3}, [%4];"
                 : "=r"(r[0]), "=r"(r[1]), "=r"(r[2]), "=r"(r[3]) : "r"(addr));
}

__device__ __forceinline__ void mma_bf16(float* d, const uint32_t* a, const uint32_t* b) {
    asm volatile(
        "mma.sync.aligned.m16n8k16.row.col.f32.bf16.bf16.f32 "
        "{%0,%1,%2,%3}, {%4,%5,%6,%7}, {%8,%9}, {%0,%1,%2,%3};"
        : "+f"(d[0]), "+f"(d[1]), "+f"(d[2]), "+f"(d[3])
        : "r"(a[0]), "r"(a[1]), "r"(a[2]), "r"(a[3]), "r"(b[0]), "r"(b[1]));
}

// ---------------- gather + weight prep (fused launch) ------------------------
__global__ __launch_bounds__(128) void gather_kernel(
    const int*   __restrict__ oh_i,  const float* __restrict__ oh_x,
    const int*   __restrict__ mi1,   const float* __restrict__ mx1,
    const int*   __restrict__ mi2,   const float* __restrict__ mx2,
    const float* __restrict__ ctns,
    const float* __restrict__ wideT, const float* __restrict__ deepT,
    const float* __restrict__ w2,    const float* __restrict__ w3,
    __nv_bfloat16* __restrict__ X,   float* __restrict__ wide_out,
    __nv_bfloat16* __restrict__ W2p, __nv_bfloat16* __restrict__ W3r)
{
    const int tid  = threadIdx.x;

    if (blockIdx.x >= BB) {
        int n = blockIdx.x - BB;
        if (n < D1) {
            for (int k = tid; k < XS; k += 128)
                W2p[(size_t)n * XS + k] = (k < D0) ? __float2bfloat16_rn(w2[(size_t)n * D0 + k])
                                                   : __float2bfloat16_rn(0.0f);
        } else {
            int m = n - D1;
            for (int k = tid; k < D1; k += 128)
                W3r[(size_t)m * D1 + k] = __float2bfloat16_rn(w3[(size_t)m * D1 + k]);
        }
        return;
    }

    const int row  = blockIdx.x;
    const int warp = tid >> 5;
    const int lane = tid & 31;
    __nv_bfloat16* xr = X + (size_t)row * XS;

    for (int f = warp; f < FF; f += 4) {
        int   idx = oh_i[row * FF + f];
        float w   = oh_x[row * FF + f];
        xr[f * EE + lane] = __float2bfloat16_rn(deepT[(size_t)idx * EE + lane] * w);
    }

    {
        const int*   mi = (warp < 2) ? mi1 : mi2;
        const float* mx = (warp < 2) ? mx1 : mx2;
        const int half  = warp & 1;
        float acc = 0.0f;
        for (int j = half; j < LL; j += 2) {
            int   idx = mi[row * LL + j];
            float w   = mx[row * LL + j];
            acc += deepT[(size_t)idx * EE + lane] * w;
        }
        __shared__ float sb[4][EE];
        sb[warp][lane] = acc;
        __syncthreads();
        if      (warp == 0) xr[FF * EE      + lane] = __float2bfloat16_rn(sb[0][lane] + sb[1][lane]);
        else if (warp == 1) xr[FF * EE + EE + lane] = __float2bfloat16_rn(sb[2][lane] + sb[3][lane]);
        else if (warp == 2) { if (lane < 13) xr[FF * EE + 2 * EE + lane] = __float2bfloat16_rn(ctns[row * 13 + lane]); }
    }
    if (tid < XS - D0) xr[D0 + tid] = __float2bfloat16_rn(0.0f);   // zero pad tail

    float wv = 0.0f;
    if (tid < FF) {
        wv = wideT[oh_i[row * FF + tid]] * oh_x[row * FF + tid];
    } else if (tid < FF + LL) {
        int j = tid - FF;
        wv = wideT[mi1[row * LL + j]] * mx1[row * LL + j];
    } else if (tid < FF + 2 * LL) {
        int j = tid - FF - LL;
        wv = wideT[mi2[row * LL + j]] * mx2[row * LL + j];
    }
    #pragma unroll
    for (int o = 16; o; o >>= 1) wv += __shfl_xor_sync(0xFFFFFFFFu, wv, o);
    __shared__ float swide[4];
    if (lane == 0) swide[warp] = wv;
    __syncthreads();
    if (tid == 0)
        wide_out[row] = swide[0] + swide[1] + swide[2] + swide[3];
}

// ---------------- bf16 mma.sync GEMM: C = A(M,K) * B(N,K)^T -----------------
// block 128x128, BK=32, 3-stage cp.async pipeline, dynamic smem 60 KB.
// 3 CTAs/SM (444 slots): GEMM1 waves 1.73 -> 1.15; 24 warps/SM.
// 8 warps as 2(M) x 4(N), warp tile 64x32.
// MODE 0: bf16 C store (bias+leaky).  MODE 1: fused layer-3 partials.
template <int MODE>
__global__ void __launch_bounds__(256, 3) bf16_gemm(
    const __nv_bfloat16* __restrict__ A, int lda,
    const __nv_bfloat16* __restrict__ Bm, int ldb,
    const float* __restrict__ bias,
    void* __restrict__ Cv, int ldc, int K,
    const float* __restrict__ w4, float* __restrict__ zp)
{
    constexpr int BM = 128, BN = 128, BK = 32, LDA = BK + 8;   // 40 bf16 = 80 B
    constexpr int ST = 3;
    constexpr int A_ELEMS = BM * LDA;
    constexpr int B_ELEMS = BN * LDA;

    extern __shared__ __align__(16) __nv_bfloat16 smem[];
    __nv_bfloat16* Asm = smem;
    __nv_bfloat16* Bsm = smem + ST * A_ELEMS;

    const int tid  = threadIdx.x;
    const int warp = tid >> 5;
    const int lane = tid & 31;
    const int wm = (warp & 1) * 64;        // 2 warps in M
    const int wn = (warp >> 1) * 32;       // 4 warps in N
    const int r  = lane >> 2;
    const int c  = lane & 3;

    const int bm = blockIdx.y * BM;
    const int bn = blockIdx.x * BN;

    const int lrow = tid >> 2;             // 0..63
    const int lcol = (tid & 3) * 8;        // 0,8,16,24
    const __nv_bfloat16* gA = A  + (size_t)(bm + lrow) * lda + lcol;
    const __nv_bfloat16* gB = Bm + (size_t)(bn + lrow) * ldb + lcol;

    uint32_t sAbase[ST], sBbase[ST];
    #pragma unroll
    for (int s = 0; s < ST; s++) {
        sAbase[s] = (uint32_t)__cvta_generic_to_shared(&Asm[s * A_ELEMS + lrow * LDA + lcol]);
        sBbase[s] = (uint32_t)__cvta_generic_to_shared(&Bsm[s * B_ELEMS + lrow * LDA + lcol]);
    }

    const int rowA_l = lane & 15;
    const int colA_l = (lane >> 4) << 3;
    const int rowB_l = (lane & 7) + ((lane & 16) >> 1);
    const int colB_l = lane & 8;
    uint32_t aBase[ST], bBase[ST];
    #pragma unroll
    for (int s = 0; s < ST; s++) {
        aBase[s] = (uint32_t)__cvta_generic_to_shared(
            &Asm[s * A_ELEMS + (wm + rowA_l) * LDA + colA_l]);
        bBase[s] = (uint32_t)__cvta_generic_to_shared(
            &Bsm[s * B_ELEMS + (wn + rowB_l) * LDA + colB_l]);
    }

    float acc[4][4][4];
    #pragma unroll
    for (int i = 0; i < 4; i++)
        #pragma unroll
        for (int j = 0; j < 4; j++)
            #pragma unroll
            for (int q = 0; q < 4; q++) acc[i][j][q] = 0.0f;

    const int T = K / BK;

    // tile loader: A/B 128 rows x 32 cols; 2 row-groups of 64 each; 4 CP16/thread
    auto load_stage = [&](int s, int k0) {
        #pragma unroll
        for (int g = 0; g < 2; g++)
            CP16(sAbase[s] + (uint32_t)(g * 64 * LDA * 2),
                 gA + (size_t)(g * 64) * lda + k0);
        #pragma unroll
        for (int g = 0; g < 2; g++)
            CP16(sBbase[s] + (uint32_t)(g * 64 * LDA * 2),
                 gB + (size_t)(g * 64) * ldb + k0);
        CPCOMMIT();
    };

    load_stage(0, 0);
    load_stage(1, BK);

    int st = 0;
    for (int t = 0; t < T; t++) {
        if (t + 1 < T) CPWAIT1(); else CPWAIT0();
        __syncthreads();

        if (t + 2 < T) {
            int ns = st + 2; if (ns >= ST) ns -= ST;
            load_stage(ns, (t + 2) * BK);
        }

        #pragma unroll
        for (int kk = 0; kk < BK; kk += 16) {
            uint32_t af[4][4], bq[2][4];
            #pragma unroll
            for (int i = 0; i < 4; i++)
                ldsm_x4(af[i], aBase[st] + (uint32_t)((16 * i * LDA + kk) * 2));
            #pragma unroll
            for (int j16 = 0; j16 < 2; j16++)
                ldsm_x4(bq[j16], bBase[st] + (uint32_t)((16 * j16 * LDA + kk) * 2));
            #pragma unroll
            for (int i = 0; i < 4; i++)
                #pragma unroll
                for (int j = 0; j < 4; j++)
                    mma_bf16(acc[i][j], af[i], &bq[j >> 1][(j & 1) * 2]);
        }
        if (++st == ST) st = 0;
    }

    if (MODE == 0) {
        // bias + leaky, bf16 store
        #pragma unroll
        for (int i = 0; i < 4; i++) {
            #pragma unroll
            for (int j = 0; j < 4; j++) {
                const int n0 = bn + wn + 8 * j + c * 2;
                const float bi0 = __ldg(&bias[n0]);
                const float bi1 = __ldg(&bias[n0 + 1]);
                #pragma unroll
                for (int h = 0; h < 2; h++) {
                    const int m = bm + wm + 16 * i + r + 8 * h;
                    float v0 = acc[i][j][2 * h + 0] + bi0;
                    float v1 = acc[i][j][2 * h + 1] + bi1;
                    v0 = (v0 >= 0.0f) ? v0 : 0.01f * v0;
                    v1 = (v1 >= 0.0f) ? v1 : 0.01f * v1;
                    __nv_bfloat162 o = make_bfloat162(__float2bfloat16_rn(v0),
                                                      __float2bfloat16_rn(v1));
                    *reinterpret_cast<__nv_bfloat162*>(
                        &((__nv_bfloat16*)Cv)[(size_t)m * ldc + n0]) = o;
                }
            }
        }
    } else {
        // fused layer-3: s[m] = sum_n leaky(acc+bias) * w4[n] over this warp's N
        float s[4][2];
        #pragma unroll
        for (int i = 0; i < 4; i++) { s[i][0] = 0.0f; s[i][1] = 0.0f; }
        #pragma unroll
        for (int j = 0; j < 4; j++) {
            const int n0 = bn + wn + 8 * j + c * 2;
            const float bi0 = __ldg(&bias[n0]);
            const float bi1 = __ldg(&bias[n0 + 1]);
            const float w0  = __ldg(&w4[n0]);
            const float w1  = __ldg(&w4[n0 + 1]);
            #pragma unroll
            for (int i = 0; i < 4; i++)
                #pragma unroll
                for (int h = 0; h < 2; h++) {
                    float v0 = acc[i][j][2 * h + 0] + bi0;
                    float v1 = acc[i][j][2 * h + 1] + bi1;
                    v0 = (v0 >= 0.0f) ? v0 : 0.01f * v0;
                    v1 = (v1 >= 0.0f) ? v1 : 0.01f * v1;
                    s[i][h] += v0 * w0 + v1 * w1;
                }
        }
        // quad reduce across c (lanes r*4 + c)
        #pragma unroll
        for (int i = 0; i < 4; i++)
            #pragma unroll
            for (int h = 0; h < 2; h++) {
                s[i][h] += __shfl_xor_sync(0xFFFFFFFFu, s[i][h], 1);
                s[i][h] += __shfl_xor_sync(0xFFFFFFFFu, s[i][h], 2);
            }
        if (c == 0) {
            const int p = blockIdx.x * 4 + (warp >> 1);
            #pragma unroll
            for (int i = 0; i < 4; i++)
                #pragma unroll
                for (int h = 0; h < 2; h++) {
                    const int m = bm + wm + 16 * i + r + 8 * h;
                    zp[(size_t)p * BB + m] = s[i][h];
                }
        }
    }
}

// ---------------- final: out = sigmoid(sum zp + b4 + 32*wide) ---------------
__global__ __launch_bounds__(128) void final_kernel(
    const float* __restrict__ zp, const float* __restrict__ b4,
    const float* __restrict__ wide, float* __restrict__ out)
{
    const int row = blockIdx.x * 128 + threadIdx.x;
    float z = b4[0] + (float)EE * wide[row];
    #pragma unroll
    for (int p = 0; p < 8; p++)
        z += zp[(size_t)p * BB + row];
    out[row] = 1.0f / (1.0f + expf(-z));
}

// ---------------- launch ----------------------------------------------------
extern "C" void kernel_launch(void* const* d_in, const int* in_sizes, int n_in,
                              void* d_out, int out_size)
{
    const int*   oh_i  = (const int*)  d_in[0];
    const float* oh_x  = (const float*)d_in[1];
    const int*   mi1   = (const int*)  d_in[2];
    const float* mx1   = (const float*)d_in[3];
    const int*   mi2   = (const int*)  d_in[4];
    const float* mx2   = (const float*)d_in[5];
    const float* ctns  = (const float*)d_in[6];
    const float* wideT = (const float*)d_in[7];
    const float* deepT = (const float*)d_in[8];
    const float* w2    = (const float*)d_in[9];
    const float* b2    = (const float*)d_in[10];
    const float* w3    = (const float*)d_in[11];
    const float* b3    = (const float*)d_in[12];
    const float* w4    = (const float*)d_in[13];
    const float* b4    = (const float*)d_in[14];
    float* out = (float*)d_out;

    __nv_bfloat16 *X, *W2p, *W3r, *H1;
    float *zp, *wide;
    cudaGetSymbolAddress((void**)&X,    g_X);
    cudaGetSymbolAddress((void**)&W2p,  g_W2p);
    cudaGetSymbolAddress((void**)&W3r,  g_W3r);
    cudaGetSymbolAddress((void**)&H1,   g_H1);
    cudaGetSymbolAddress((void**)&zp,   g_zp);
    cudaGetSymbolAddress((void**)&wide, g_wide);

    const int SMEM = 3 * (128 + 128) * 40 * 2;   // 61440 bytes
    static int attr_done = 0;
    if (!attr_done) {
        cudaFuncSetAttribute(bf16_gemm<0>,
                             cudaFuncAttributeMaxDynamicSharedMemorySize, SMEM);
        cudaFuncSetAttribute(bf16_gemm<1>,
                             cudaFuncAttributeMaxDynamicSharedMemorySize, SMEM);
        attr_done = 1;
    }

    // fused gather + weight prep
    gather_kernel<<<BB + D1 + D2, 128>>>(oh_i, oh_x, mi1, mx1, mi2, mx2, ctns,
                                         wideT, deepT, w2, w3,
                                         X, wide, W2p, W3r);

    // layer 1: [B,928] x [512,928]^T -> H1[B,512] bf16
    bf16_gemm<0><<<dim3(D1 / 128, BB / 128), 256, SMEM>>>(
        X, XS, W2p, XS, b2, (void*)H1, D1, XS, nullptr, nullptr);

    // layer 2 + layer 3 (fused): [B,512] x [256,512]^T -> zp[8][B]
    bf16_gemm<1><<<dim3(D2 / 128, BB / 128), 256, SMEM>>>(
        H1, D1, W3r, D1, b3, nullptr, D2, D1, w4, zp);

    // sigmoid( sum(zp) + b4 + 32*wide )
    final_kernel<<<BB / 128, 128>>>(zp, b4, wide, out);
}

// round 14
// speedup vs baseline: 1.3200x; 1.3200x over previous
#include <cuda_runtime.h>
#include <cuda_bf16.h>
#include <math.h>
#include <stdint.h>

// ---------------- problem constants ----------------
#define BB 16384      // batch
#define FF 26         // onehot fields
#define EE 32         // embedding dim
#define LL 50         // bag length
#define D0 909
#define D1 512
#define D2 256
#define XS 960        // D0 padded (zero tail), multiple of 64
#define WPREP (D1 + D2)   // weight-prep blocks (run first)

// ---------------- scratch (static device globals: allocation-free) ----------
__device__ __nv_bfloat16 g_X  [(size_t)BB * XS];   // activations bf16
__device__ __nv_bfloat16 g_W2p[(size_t)D1 * XS];   // padded w2 bf16
__device__ __nv_bfloat16 g_W3r[(size_t)D2 * D1];   // w3 bf16
__device__ __nv_bfloat16 g_H1 [(size_t)BB * D1];   // layer-1 out bf16
__device__ float         g_zp [(size_t)8 * BB];    // fused layer-3 partials [8][B]
__device__ float         g_wide[BB];

// ---------------- helpers ----------------------------------------------------
#define CP16(dst, src) \
    asm volatile("cp.async.cg.shared.global [%0], [%1], 16;\n" :: "r"(dst), "l"(src))
#define CPCOMMIT() asm volatile("cp.async.commit_group;\n" ::)
#define CPWAIT0()  asm volatile("cp.async.wait_group 0;\n" ::)
#define CPWAIT1()  asm volatile("cp.async.wait_group 1;\n" ::)

__device__ __forceinline__ void ldsm_x4(uint32_t* r, uint32_t addr) {
    asm volatile("ldmatrix.sync.aligned.m8n8.x4.shared.b16 {%0,%1,%2,%3}, [%4];"
                 : "=r"(r[0]), "=r"(r[1]), "=r"(r[2]), "=r"(r[3]) : "r"(addr));
}

__device__ __forceinline__ void mma_bf16(float* d, const uint32_t* a, const uint32_t* b) {
    asm volatile(
        "mma.sync.aligned.m16n8k16.row.col.f32.bf16.bf16.f32 "
        "{%0,%1,%2,%3}, {%4,%5,%6,%7}, {%8,%9}, {%0,%1,%2,%3};"
        : "+f"(d[0]), "+f"(d[1]), "+f"(d[2]), "+f"(d[3])
        : "r"(a[0]), "r"(a[1]), "r"(a[2]), "r"(a[3]), "r"(b[0]), "r"(b[1]));
}

// streaming bf16 store (evict-first): protect deep_table L2 residency
__device__ __forceinline__ void st_cs_bf16(__nv_bfloat16* p, float v) {
    __nv_bfloat16 b = __float2bfloat16_rn(v);
    unsigned short u;
    memcpy(&u, &b, 2);
    asm volatile("st.global.cs.u16 [%0], %1;" :: "l"(p), "h"(u) : "memory");
}

// ---------------- gather + weight prep (fused launch) ------------------------
// blocks [0, WPREP): weight prep (first, so GEMM1 inputs ready earliest).
// blocks [WPREP, WPREP+BB): gather one batch row each.
__global__ __launch_bounds__(128) void gather_kernel(
    const int*   __restrict__ oh_i,  const float* __restrict__ oh_x,
    const int*   __restrict__ mi1,   const float* __restrict__ mx1,
    const int*   __restrict__ mi2,   const float* __restrict__ mx2,
    const float* __restrict__ ctns,
    const float* __restrict__ wideT, const float* __restrict__ deepT,
    const float* __restrict__ w2,    const float* __restrict__ w3,
    __nv_bfloat16* __restrict__ X,   float* __restrict__ wide_out,
    __nv_bfloat16* __restrict__ W2p, __nv_bfloat16* __restrict__ W3r)
{
    const int tid  = threadIdx.x;

    if (blockIdx.x < WPREP) {
        int n = blockIdx.x;
        if (n < D1) {
            for (int k = tid; k < XS; k += 128)
                W2p[(size_t)n * XS + k] = (k < D0) ? __float2bfloat16_rn(w2[(size_t)n * D0 + k])
                                                   : __float2bfloat16_rn(0.0f);
        } else {
            int m = n - D1;
            for (int k = tid; k < D1; k += 128)
                W3r[(size_t)m * D1 + k] = __float2bfloat16_rn(w3[(size_t)m * D1 + k]);
        }
        return;
    }

    const int row  = blockIdx.x - WPREP;
    const int warp = tid >> 5;
    const int lane = tid & 31;
    __nv_bfloat16* xr = X + (size_t)row * XS;

    for (int f = warp; f < FF; f += 4) {
        int   idx = oh_i[row * FF + f];
        float w   = oh_x[row * FF + f];
        st_cs_bf16(&xr[f * EE + lane], deepT[(size_t)idx * EE + lane] * w);
    }

    {
        const int*   mi = (warp < 2) ? mi1 : mi2;
        const float* mx = (warp < 2) ? mx1 : mx2;
        const int half  = warp & 1;
        float acc = 0.0f;
        for (int j = half; j < LL; j += 2) {
            int   idx = mi[row * LL + j];
            float w   = mx[row * LL + j];
            acc += deepT[(size_t)idx * EE + lane] * w;
        }
        __shared__ float sb[4][EE];
        sb[warp][lane] = acc;
        __syncthreads();
        if      (warp == 0) st_cs_bf16(&xr[FF * EE      + lane], sb[0][lane] + sb[1][lane]);
        else if (warp == 1) st_cs_bf16(&xr[FF * EE + EE + lane], sb[2][lane] + sb[3][lane]);
        else if (warp == 2) { if (lane < 13) st_cs_bf16(&xr[FF * EE + 2 * EE + lane], ctns[row * 13 + lane]); }
    }
    if (tid < XS - D0) st_cs_bf16(&xr[D0 + tid], 0.0f);   // zero pad tail

    float wv = 0.0f;
    if (tid < FF) {
        wv = wideT[oh_i[row * FF + tid]] * oh_x[row * FF + tid];
    } else if (tid < FF + LL) {
        int j = tid - FF;
        wv = wideT[mi1[row * LL + j]] * mx1[row * LL + j];
    } else if (tid < FF + 2 * LL) {
        int j = tid - FF - LL;
        wv = wideT[mi2[row * LL + j]] * mx2[row * LL + j];
    }
    #pragma unroll
    for (int o = 16; o; o >>= 1) wv += __shfl_xor_sync(0xFFFFFFFFu, wv, o);
    __shared__ float swide[4];
    if (lane == 0) swide[warp] = wv;
    __syncthreads();
    if (tid == 0)
        wide_out[row] = swide[0] + swide[1] + swide[2] + swide[3];
}

// ---------------- bf16 mma.sync GEMM: C = A(M,K) * B(N,K)^T -----------------
// block 128x128, BK=64, 3-stage cp.async pipeline, dynamic smem (108 KB).
// 8 warps as 2(M) x 4(N), warp tile 64x32; register double-buffered fragments.
// MODE 0: bf16 C store (bias+leaky).  MODE 1: fused layer-3 partials.
template <int MODE>
__global__ void __launch_bounds__(256, 2) bf16_gemm(
    const __nv_bfloat16* __restrict__ A, int lda,
    const __nv_bfloat16* __restrict__ Bm, int ldb,
    const float* __restrict__ bias,
    void* __restrict__ Cv, int ldc, int K,
    const float* __restrict__ w4, float* __restrict__ zp)
{
    constexpr int BM = 128, BN = 128, BK = 64, LDA = BK + 8;   // 72 bf16 = 144 B
    constexpr int ST = 3;
    constexpr int A_ELEMS = BM * LDA;
    constexpr int B_ELEMS = BN * LDA;

    extern __shared__ __align__(16) __nv_bfloat16 smem[];
    __nv_bfloat16* Asm = smem;
    __nv_bfloat16* Bsm = smem + ST * A_ELEMS;

    const int tid  = threadIdx.x;
    const int warp = tid >> 5;
    const int lane = tid & 31;
    const int wm = (warp & 1) * 64;        // 2 warps in M
    const int wn = (warp >> 1) * 32;       // 4 warps in N
    const int r  = lane >> 2;
    const int c  = lane & 3;

    const int bm = blockIdx.y * BM;
    const int bn = blockIdx.x * BN;

    const int lrow = tid >> 3;             // 0..31
    const int lcol = (tid & 7) * 8;        // 0..56
    const __nv_bfloat16* gA = A  + (size_t)(bm + lrow) * lda + lcol;
    const __nv_bfloat16* gB = Bm + (size_t)(bn + lrow) * ldb + lcol;

    uint32_t sAbase[ST], sBbase[ST];
    #pragma unroll
    for (int s = 0; s < ST; s++) {
        sAbase[s] = (uint32_t)__cvta_generic_to_shared(&Asm[s * A_ELEMS + lrow * LDA + lcol]);
        sBbase[s] = (uint32_t)__cvta_generic_to_shared(&Bsm[s * B_ELEMS + lrow * LDA + lcol]);
    }

    const int rowA_l = lane & 15;
    const int colA_l = (lane >> 4) << 3;
    const int rowB_l = (lane & 7) + ((lane & 16) >> 1);
    const int colB_l = lane & 8;
    uint32_t aBase[ST], bBase[ST];
    #pragma unroll
    for (int s = 0; s < ST; s++) {
        aBase[s] = (uint32_t)__cvta_generic_to_shared(
            &Asm[s * A_ELEMS + (wm + rowA_l) * LDA + colA_l]);
        bBase[s] = (uint32_t)__cvta_generic_to_shared(
            &Bsm[s * B_ELEMS + (wn + rowB_l) * LDA + colB_l]);
    }

    float acc[4][4][4];
    #pragma unroll
    for (int i = 0; i < 4; i++)
        #pragma unroll
        for (int j = 0; j < 4; j++)
            #pragma unroll
            for (int q = 0; q < 4; q++) acc[i][j][q] = 0.0f;

    const int T = K / BK;

    auto load_stage = [&](int s, int k0) {
        #pragma unroll
        for (int g = 0; g < 4; g++)
            CP16(sAbase[s] + (uint32_t)(g * 32 * LDA * 2),
                 gA + (size_t)(g * 32) * lda + k0);
        #pragma unroll
        for (int g = 0; g < 4; g++)
            CP16(sBbase[s] + (uint32_t)(g * 32 * LDA * 2),
                 gB + (size_t)(g * 32) * ldb + k0);
        CPCOMMIT();
    };

    load_stage(0, 0);
    load_stage(1, BK);

    uint32_t af[2][4][4], bq[2][2][4];

    int st = 0;
    for (int t = 0; t < T; t++) {
        if (t + 1 < T) CPWAIT1(); else CPWAIT0();
        __syncthreads();

        if (t + 2 < T) {
            int ns = st + 2; if (ns >= ST) ns -= ST;
            load_stage(ns, (t + 2) * BK);
        }

        // fragment set 0 for kk=0
        #pragma unroll
        for (int i = 0; i < 4; i++)
            ldsm_x4(af[0][i], aBase[st] + (uint32_t)((16 * i * LDA) * 2));
        #pragma unroll
        for (int j16 = 0; j16 < 2; j16++)
            ldsm_x4(bq[0][j16], bBase[st] + (uint32_t)((16 * j16 * LDA) * 2));

        int cur = 0;
        #pragma unroll
        for (int kk = 0; kk < BK; kk += 16) {
            const int nxt = cur ^ 1;
            if (kk + 16 < BK) {       // prefetch next slab's fragments
                #pragma unroll
                for (int i = 0; i < 4; i++)
                    ldsm_x4(af[nxt][i], aBase[st] + (uint32_t)((16 * i * LDA + kk + 16) * 2));
                #pragma unroll
                for (int j16 = 0; j16 < 2; j16++)
                    ldsm_x4(bq[nxt][j16], bBase[st] + (uint32_t)((16 * j16 * LDA + kk + 16) * 2));
            }
            #pragma unroll
            for (int i = 0; i < 4; i++)
                #pragma unroll
                for (int j = 0; j < 4; j++)
                    mma_bf16(acc[i][j], af[cur][i], &bq[cur][j >> 1][(j & 1) * 2]);
            cur = nxt;
        }
        if (++st == ST) st = 0;
    }

    if (MODE == 0) {
        // bias + leaky, bf16 store
        #pragma unroll
        for (int i = 0; i < 4; i++) {
            #pragma unroll
            for (int j = 0; j < 4; j++) {
                const int n0 = bn + wn + 8 * j + c * 2;
                const float bi0 = __ldg(&bias[n0]);
                const float bi1 = __ldg(&bias[n0 + 1]);
                #pragma unroll
                for (int h = 0; h < 2; h++) {
                    const int m = bm + wm + 16 * i + r + 8 * h;
                    float v0 = acc[i][j][2 * h + 0] + bi0;
                    float v1 = acc[i][j][2 * h + 1] + bi1;
                    v0 = (v0 >= 0.0f) ? v0 : 0.01f * v0;
                    v1 = (v1 >= 0.0f) ? v1 : 0.01f * v1;
                    __nv_bfloat162 o = make_bfloat162(__float2bfloat16_rn(v0),
                                                      __float2bfloat16_rn(v1));
                    *reinterpret_cast<__nv_bfloat162*>(
                        &((__nv_bfloat16*)Cv)[(size_t)m * ldc + n0]) = o;
                }
            }
        }
    } else {
        // fused layer-3: s[m] = sum_n leaky(acc+bias) * w4[n] over this warp's N
        float s[4][2];
        #pragma unroll
        for (int i = 0; i < 4; i++) { s[i][0] = 0.0f; s[i][1] = 0.0f; }
        #pragma unroll
        for (int j = 0; j < 4; j++) {
            const int n0 = bn + wn + 8 * j + c * 2;
            const float bi0 = __ldg(&bias[n0]);
            const float bi1 = __ldg(&bias[n0 + 1]);
            const float w0  = __ldg(&w4[n0]);
            const float w1  = __ldg(&w4[n0 + 1]);
            #pragma unroll
            for (int i = 0; i < 4; i++)
                #pragma unroll
                for (int h = 0; h < 2; h++) {
                    float v0 = acc[i][j][2 * h + 0] + bi0;
                    float v1 = acc[i][j][2 * h + 1] + bi1;
                    v0 = (v0 >= 0.0f) ? v0 : 0.01f * v0;
                    v1 = (v1 >= 0.0f) ? v1 : 0.01f * v1;
                    s[i][h] += v0 * w0 + v1 * w1;
                }
        }
        // quad reduce across c (lanes r*4 + c)
        #pragma unroll
        for (int i = 0; i < 4; i++)
            #pragma unroll
            for (int h = 0; h < 2; h++) {
                s[i][h] += __shfl_xor_sync(0xFFFFFFFFu, s[i][h], 1);
                s[i][h] += __shfl_xor_sync(0xFFFFFFFFu, s[i][h], 2);
            }
        if (c == 0) {
            const int p = blockIdx.x * 4 + (warp >> 1);
            #pragma unroll
            for (int i = 0; i < 4; i++)
                #pragma unroll
                for (int h = 0; h < 2; h++) {
                    const int m = bm + wm + 16 * i + r + 8 * h;
                    zp[(size_t)p * BB + m] = s[i][h];
                }
        }
    }
}

// ---------------- final: out = sigmoid(sum zp + b4 + 32*wide) ---------------
__global__ __launch_bounds__(128) void final_kernel(
    const float* __restrict__ zp, const float* __restrict__ b4,
    const float* __restrict__ wide, float* __restrict__ out)
{
    const int row = blockIdx.x * 128 + threadIdx.x;
    float z = b4[0] + (float)EE * wide[row];
    #pragma unroll
    for (int p = 0; p < 8; p++)
        z += zp[(size_t)p * BB + row];
    out[row] = 1.0f / (1.0f + expf(-z));
}

// ---------------- launch ----------------------------------------------------
extern "C" void kernel_launch(void* const* d_in, const int* in_sizes, int n_in,
                              void* d_out, int out_size)
{
    const int*   oh_i  = (const int*)  d_in[0];
    const float* oh_x  = (const float*)d_in[1];
    const int*   mi1   = (const int*)  d_in[2];
    const float* mx1   = (const float*)d_in[3];
    const int*   mi2   = (const int*)  d_in[4];
    const float* mx2   = (const float*)d_in[5];
    const float* ctns  = (const float*)d_in[6];
    const float* wideT = (const float*)d_in[7];
    const float* deepT = (const float*)d_in[8];
    const float* w2    = (const float*)d_in[9];
    const float* b2    = (const float*)d_in[10];
    const float* w3    = (const float*)d_in[11];
    const float* b3    = (const float*)d_in[12];
    const float* w4    = (const float*)d_in[13];
    const float* b4    = (const float*)d_in[14];
    float* out = (float*)d_out;

    __nv_bfloat16 *X, *W2p, *W3r, *H1;
    float *zp, *wide;
    cudaGetSymbolAddress((void**)&X,    g_X);
    cudaGetSymbolAddress((void**)&W2p,  g_W2p);
    cudaGetSymbolAddress((void**)&W3r,  g_W3r);
    cudaGetSymbolAddress((void**)&H1,   g_H1);
    cudaGetSymbolAddress((void**)&zp,   g_zp);
    cudaGetSymbolAddress((void**)&wide, g_wide);

    const int SMEM = 3 * (128 + 128) * 72 * 2;   // 110592 bytes
    cudaFuncSetAttribute(bf16_gemm<0>,
                         cudaFuncAttributeMaxDynamicSharedMemorySize, SMEM);
    cudaFuncSetAttribute(bf16_gemm<1>,
                         cudaFuncAttributeMaxDynamicSharedMemorySize, SMEM);

    // fused weight prep (first) + gather
    gather_kernel<<<WPREP + BB, 128>>>(oh_i, oh_x, mi1, mx1, mi2, mx2, ctns,
                                       wideT, deepT, w2, w3,
                                       X, wide, W2p, W3r);

    // layer 1: [B,960] x [512,960]^T -> H1[B,512] bf16
    bf16_gemm<0><<<dim3(D1 / 128, BB / 128), 256, SMEM>>>(
        X, XS, W2p, XS, b2, (void*)H1, D1, XS, nullptr, nullptr);

    // layer 2 + layer 3 (fused): [B,512] x [256,512]^T -> zp[8][B]
    bf16_gemm<1><<<dim3(D2 / 128, BB / 128), 256, SMEM>>>(
        H1, D1, W3r, D1, b3, nullptr, D2, D1, w4, zp);

    // sigmoid( sum(zp) + b4 + 32*wide )
    final_kernel<<<BB / 128, 128>>>(zp, b4, wide, out);
}

// round 16
// speedup vs baseline: 1.3482x; 1.0213x over previous
#include <cuda_runtime.h>
#include <cuda_bf16.h>
#include <math.h>
#include <stdint.h>

// ---------------- problem constants ----------------
#define BB 16384      // batch
#define FF 26         // onehot fields
#define EE 32         // embedding dim
#define LL 50         // bag length
#define D0 909
#define D1 512
#define D2 256
#define XS 960        // D0 padded (zero tail), multiple of 64

// ---------------- scratch (static device globals: allocation-free) ----------
__device__ __nv_bfloat16 g_X  [(size_t)BB * XS];   // activations bf16
__device__ __nv_bfloat16 g_W2p[(size_t)D1 * XS];   // padded w2 bf16
__device__ __nv_bfloat16 g_W3r[(size_t)D2 * D1];   // w3 bf16
__device__ __nv_bfloat16 g_H1 [(size_t)BB * D1];   // layer-1 out bf16
__device__ float         g_zp [(size_t)8 * BB];    // fused layer-3 partials [8][B]
__device__ float         g_wide[BB];

// ---------------- helpers ----------------------------------------------------
#define CP16(dst, src) \
    asm volatile("cp.async.cg.shared.global [%0], [%1], 16;\n" :: "r"(dst), "l"(src))
#define CPCOMMIT() asm volatile("cp.async.commit_group;\n" ::)
#define CPWAIT0()  asm volatile("cp.async.wait_group 0;\n" ::)
#define CPWAIT1()  asm volatile("cp.async.wait_group 1;\n" ::)

__device__ __forceinline__ void ldsm_x4(uint32_t* r, uint32_t addr) {
    asm volatile("ldmatrix.sync.aligned.m8n8.x4.shared.b16 {%0,%1,%2,%3}, [%4];"
                 : "=r"(r[0]), "=r"(r[1]), "=r"(r[2]), "=r"(r[3]) : "r"(addr));
}

__device__ __forceinline__ void mma_bf16(float* d, const uint32_t* a, const uint32_t* b) {
    asm volatile(
        "mma.sync.aligned.m16n8k16.row.col.f32.bf16.bf16.f32 "
        "{%0,%1,%2,%3}, {%4,%5,%6,%7}, {%8,%9}, {%0,%1,%2,%3};"
        : "+f"(d[0]), "+f"(d[1]), "+f"(d[2]), "+f"(d[3])
        : "r"(a[0]), "r"(a[1]), "r"(a[2]), "r"(a[3]), "r"(b[0]), "r"(b[1]));
}

// L2 evict_last policy (created once per thread); cache_hint form accepts
// scalar widths, unlike the direct .L2::evict_last qualifier (v8-only here).
__device__ __forceinline__ uint64_t mk_policy_el() {
    uint64_t pol;
    asm volatile("createpolicy.fractional.L2::evict_last.b64 %0, 1.0;" : "=l"(pol));
    return pol;
}
__device__ __forceinline__ float ldg_el(const float* p, uint64_t pol) {
    float v;
    asm volatile("ld.global.nc.L2::cache_hint.f32 %0, [%1], %2;"
                 : "=f"(v) : "l"(p), "l"(pol));
    return v;
}

// ---------------- gather + weight prep (fused launch) ------------------------
__global__ __launch_bounds__(128) void gather_kernel(
    const int*   __restrict__ oh_i,  const float* __restrict__ oh_x,
    const int*   __restrict__ mi1,   const float* __restrict__ mx1,
    const int*   __restrict__ mi2,   const float* __restrict__ mx2,
    const float* __restrict__ ctns,
    const float* __restrict__ wideT, const float* __restrict__ deepT,
    const float* __restrict__ w2,    const float* __restrict__ w3,
    __nv_bfloat16* __restrict__ X,   float* __restrict__ wide_out,
    __nv_bfloat16* __restrict__ W2p, __nv_bfloat16* __restrict__ W3r)
{
    const int tid  = threadIdx.x;

    if (blockIdx.x >= BB) {
        int n = blockIdx.x - BB;
        if (n < D1) {
            for (int k = tid; k < XS; k += 128)
                W2p[(size_t)n * XS + k] = (k < D0) ? __float2bfloat16_rn(w2[(size_t)n * D0 + k])
                                                   : __float2bfloat16_rn(0.0f);
        } else {
            int m = n - D1;
            for (int k = tid; k < D1; k += 128)
                W3r[(size_t)m * D1 + k] = __float2bfloat16_rn(w3[(size_t)m * D1 + k]);
        }
        return;
    }

    const int row  = blockIdx.x;
    const int warp = tid >> 5;
    const int lane = tid & 31;
    __nv_bfloat16* xr = X + (size_t)row * XS;
    const uint64_t pol = mk_policy_el();

    for (int f = warp; f < FF; f += 4) {
        int   idx = oh_i[row * FF + f];
        float w   = oh_x[row * FF + f];
        xr[f * EE + lane] = __float2bfloat16_rn(ldg_el(&deepT[(size_t)idx * EE + lane], pol) * w);
    }

    {
        const int*   mi = (warp < 2) ? mi1 : mi2;
        const float* mx = (warp < 2) ? mx1 : mx2;
        const int half  = warp & 1;
        float acc = 0.0f;
        for (int j = half; j < LL; j += 2) {
            int   idx = mi[row * LL + j];
            float w   = mx[row * LL + j];
            acc += ldg_el(&deepT[(size_t)idx * EE + lane], pol) * w;
        }
        __shared__ float sb[4][EE];
        sb[warp][lane] = acc;
        __syncthreads();
        if      (warp == 0) xr[FF * EE      + lane] = __float2bfloat16_rn(sb[0][lane] + sb[1][lane]);
        else if (warp == 1) xr[FF * EE + EE + lane] = __float2bfloat16_rn(sb[2][lane] + sb[3][lane]);
        else if (warp == 2) { if (lane < 13) xr[FF * EE + 2 * EE + lane] = __float2bfloat16_rn(ctns[row * 13 + lane]); }
    }
    if (tid < XS - D0) xr[D0 + tid] = __float2bfloat16_rn(0.0f);   // zero pad tail

    float wv = 0.0f;
    if (tid < FF) {
        wv = wideT[oh_i[row * FF + tid]] * oh_x[row * FF + tid];
    } else if (tid < FF + LL) {
        int j = tid - FF;
        wv = wideT[mi1[row * LL + j]] * mx1[row * LL + j];
    } else if (tid < FF + 2 * LL) {
        int j = tid - FF - LL;
        wv = wideT[mi2[row * LL + j]] * mx2[row * LL + j];
    }
    #pragma unroll
    for (int o = 16; o; o >>= 1) wv += __shfl_xor_sync(0xFFFFFFFFu, wv, o);
    __shared__ float swide[4];
    if (lane == 0) swide[warp] = wv;
    __syncthreads();
    if (tid == 0)
        wide_out[row] = swide[0] + swide[1] + swide[2] + swide[3];
}

// ---------------- bf16 mma.sync GEMM: C = A(M,K) * B(N,K)^T -----------------
// block 128x128, BK=64, 3-stage cp.async pipeline, dynamic smem (108 KB).
// 8 warps as 2(M) x 4(N), warp tile 64x32; register double-buffered fragments.
// MODE 0: bf16 C store (bias+leaky).  MODE 1: fused layer-3 partials.
template <int MODE>
__global__ void __launch_bounds__(256, 2) bf16_gemm(
    const __nv_bfloat16* __restrict__ A, int lda,
    const __nv_bfloat16* __restrict__ Bm, int ldb,
    const float* __restrict__ bias,
    void* __restrict__ Cv, int ldc, int K,
    const float* __restrict__ w4, float* __restrict__ zp)
{
    constexpr int BM = 128, BN = 128, BK = 64, LDA = BK + 8;   // 72 bf16 = 144 B
    constexpr int ST = 3;
    constexpr int A_ELEMS = BM * LDA;
    constexpr int B_ELEMS = BN * LDA;

    extern __shared__ __align__(16) __nv_bfloat16 smem[];
    __nv_bfloat16* Asm = smem;
    __nv_bfloat16* Bsm = smem + ST * A_ELEMS;

    const int tid  = threadIdx.x;
    const int warp = tid >> 5;
    const int lane = tid & 31;
    const int wm = (warp & 1) * 64;        // 2 warps in M
    const int wn = (warp >> 1) * 32;       // 4 warps in N
    const int r  = lane >> 2;
    const int c  = lane & 3;

    const int bm = blockIdx.y * BM;
    const int bn = blockIdx.x * BN;

    const int lrow = tid >> 3;             // 0..31
    const int lcol = (tid & 7) * 8;        // 0..56
    const __nv_bfloat16* gA = A  + (size_t)(bm + lrow) * lda + lcol;
    const __nv_bfloat16* gB = Bm + (size_t)(bn + lrow) * ldb + lcol;

    uint32_t sAbase[ST], sBbase[ST];
    #pragma unroll
    for (int s = 0; s < ST; s++) {
        sAbase[s] = (uint32_t)__cvta_generic_to_shared(&Asm[s * A_ELEMS + lrow * LDA + lcol]);
        sBbase[s] = (uint32_t)__cvta_generic_to_shared(&Bsm[s * B_ELEMS + lrow * LDA + lcol]);
    }

    const int rowA_l = lane & 15;
    const int colA_l = (lane >> 4) << 3;
    const int rowB_l = (lane & 7) + ((lane & 16) >> 1);
    const int colB_l = lane & 8;
    uint32_t aBase[ST], bBase[ST];
    #pragma unroll
    for (int s = 0; s < ST; s++) {
        aBase[s] = (uint32_t)__cvta_generic_to_shared(
            &Asm[s * A_ELEMS + (wm + rowA_l) * LDA + colA_l]);
        bBase[s] = (uint32_t)__cvta_generic_to_shared(
            &Bsm[s * B_ELEMS + (wn + rowB_l) * LDA + colB_l]);
    }

    float acc[4][4][4];
    #pragma unroll
    for (int i = 0; i < 4; i++)
        #pragma unroll
        for (int j = 0; j < 4; j++)
            #pragma unroll
            for (int q = 0; q < 4; q++) acc[i][j][q] = 0.0f;

    const int T = K / BK;

    auto load_stage = [&](int s, int k0) {
        #pragma unroll
        for (int g = 0; g < 4; g++)
            CP16(sAbase[s] + (uint32_t)(g * 32 * LDA * 2),
                 gA + (size_t)(g * 32) * lda + k0);
        #pragma unroll
        for (int g = 0; g < 4; g++)
            CP16(sBbase[s] + (uint32_t)(g * 32 * LDA * 2),
                 gB + (size_t)(g * 32) * ldb + k0);
        CPCOMMIT();
    };

    load_stage(0, 0);
    load_stage(1, BK);

    uint32_t af[2][4][4], bq[2][2][4];

    int st = 0;
    for (int t = 0; t < T; t++) {
        if (t + 1 < T) CPWAIT1(); else CPWAIT0();
        __syncthreads();

        if (t + 2 < T) {
            int ns = st + 2; if (ns >= ST) ns -= ST;
            load_stage(ns, (t + 2) * BK);
        }

        // fragment set 0 for kk=0
        #pragma unroll
        for (int i = 0; i < 4; i++)
            ldsm_x4(af[0][i], aBase[st] + (uint32_t)((16 * i * LDA) * 2));
        #pragma unroll
        for (int j16 = 0; j16 < 2; j16++)
            ldsm_x4(bq[0][j16], bBase[st] + (uint32_t)((16 * j16 * LDA) * 2));

        int cur = 0;
        #pragma unroll
        for (int kk = 0; kk < BK; kk += 16) {
            const int nxt = cur ^ 1;
            if (kk + 16 < BK) {       // prefetch next slab's fragments
                #pragma unroll
                for (int i = 0; i < 4; i++)
                    ldsm_x4(af[nxt][i], aBase[st] + (uint32_t)((16 * i * LDA + kk + 16) * 2));
                #pragma unroll
                for (int j16 = 0; j16 < 2; j16++)
                    ldsm_x4(bq[nxt][j16], bBase[st] + (uint32_t)((16 * j16 * LDA + kk + 16) * 2));
            }
            #pragma unroll
            for (int i = 0; i < 4; i++)
                #pragma unroll
                for (int j = 0; j < 4; j++)
                    mma_bf16(acc[i][j], af[cur][i], &bq[cur][j >> 1][(j & 1) * 2]);
            cur = nxt;
        }
        if (++st == ST) st = 0;
    }

    if (MODE == 0) {
        // bias + leaky, bf16 store
        #pragma unroll
        for (int i = 0; i < 4; i++) {
            #pragma unroll
            for (int j = 0; j < 4; j++) {
                const int n0 = bn + wn + 8 * j + c * 2;
                const float bi0 = __ldg(&bias[n0]);
                const float bi1 = __ldg(&bias[n0 + 1]);
                #pragma unroll
                for (int h = 0; h < 2; h++) {
                    const int m = bm + wm + 16 * i + r + 8 * h;
                    float v0 = acc[i][j][2 * h + 0] + bi0;
                    float v1 = acc[i][j][2 * h + 1] + bi1;
                    v0 = (v0 >= 0.0f) ? v0 : 0.01f * v0;
                    v1 = (v1 >= 0.0f) ? v1 : 0.01f * v1;
                    __nv_bfloat162 o = make_bfloat162(__float2bfloat16_rn(v0),
                                                      __float2bfloat16_rn(v1));
                    *reinterpret_cast<__nv_bfloat162*>(
                        &((__nv_bfloat16*)Cv)[(size_t)m * ldc + n0]) = o;
                }
            }
        }
    } else {
        // fused layer-3: s[m] = sum_n leaky(acc+bias) * w4[n] over this warp's N
        float s[4][2];
        #pragma unroll
        for (int i = 0; i < 4; i++) { s[i][0] = 0.0f; s[i][1] = 0.0f; }
        #pragma unroll
        for (int j = 0; j < 4; j++) {
            const int n0 = bn + wn + 8 * j + c * 2;
            const float bi0 = __ldg(&bias[n0]);
            const float bi1 = __ldg(&bias[n0 + 1]);
            const float w0  = __ldg(&w4[n0]);
            const float w1  = __ldg(&w4[n0 + 1]);
            #pragma unroll
            for (int i = 0; i < 4; i++)
                #pragma unroll
                for (int h = 0; h < 2; h++) {
                    float v0 = acc[i][j][2 * h + 0] + bi0;
                    float v1 = acc[i][j][2 * h + 1] + bi1;
                    v0 = (v0 >= 0.0f) ? v0 : 0.01f * v0;
                    v1 = (v1 >= 0.0f) ? v1 : 0.01f * v1;
                    s[i][h] += v0 * w0 + v1 * w1;
                }
        }
        // quad reduce across c (lanes r*4 + c)
        #pragma unroll
        for (int i = 0; i < 4; i++)
            #pragma unroll
            for (int h = 0; h < 2; h++) {
                s[i][h] += __shfl_xor_sync(0xFFFFFFFFu, s[i][h], 1);
                s[i][h] += __shfl_xor_sync(0xFFFFFFFFu, s[i][h], 2);
            }
        if (c == 0) {
            const int p = blockIdx.x * 4 + (warp >> 1);
            #pragma unroll
            for (int i = 0; i < 4; i++)
                #pragma unroll
                for (int h = 0; h < 2; h++) {
                    const int m = bm + wm + 16 * i + r + 8 * h;
                    zp[(size_t)p * BB + m] = s[i][h];
                }
        }
    }
}

// ---------------- final: out = sigmoid(sum zp + b4 + 32*wide) ---------------
__global__ __launch_bounds__(128) void final_kernel(
    const float* __restrict__ zp, const float* __restrict__ b4,
    const float* __restrict__ wide, float* __restrict__ out)
{
    const int row = blockIdx.x * 128 + threadIdx.x;
    float z = b4[0] + (float)EE * wide[row];
    #pragma unroll
    for (int p = 0; p < 8; p++)
        z += zp[(size_t)p * BB + row];
    out[row] = 1.0f / (1.0f + expf(-z));
}

// ---------------- launch ----------------------------------------------------
extern "C" void kernel_launch(void* const* d_in, const int* in_sizes, int n_in,
                              void* d_out, int out_size)
{
    const int*   oh_i  = (const int*)  d_in[0];
    const float* oh_x  = (const float*)d_in[1];
    const int*   mi1   = (const int*)  d_in[2];
    const float* mx1   = (const float*)d_in[3];
    const int*   mi2   = (const int*)  d_in[4];
    const float* mx2   = (const float*)d_in[5];
    const float* ctns  = (const float*)d_in[6];
    const float* wideT = (const float*)d_in[7];
    const float* deepT = (const float*)d_in[8];
    const float* w2    = (const float*)d_in[9];
    const float* b2    = (const float*)d_in[10];
    const float* w3    = (const float*)d_in[11];
    const float* b3    = (const float*)d_in[12];
    const float* w4    = (const float*)d_in[13];
    const float* b4    = (const float*)d_in[14];
    float* out = (float*)d_out;

    __nv_bfloat16 *X, *W2p, *W3r, *H1;
    float *zp, *wide;
    cudaGetSymbolAddress((void**)&X,    g_X);
    cudaGetSymbolAddress((void**)&W2p,  g_W2p);
    cudaGetSymbolAddress((void**)&W3r,  g_W3r);
    cudaGetSymbolAddress((void**)&H1,   g_H1);
    cudaGetSymbolAddress((void**)&zp,   g_zp);
    cudaGetSymbolAddress((void**)&wide, g_wide);

    const int SMEM = 3 * (128 + 128) * 72 * 2;   // 110592 bytes
    cudaFuncSetAttribute(bf16_gemm<0>,
                         cudaFuncAttributeMaxDynamicSharedMemorySize, SMEM);
    cudaFuncSetAttribute(bf16_gemm<1>,
                         cudaFuncAttributeMaxDynamicSharedMemorySize, SMEM);

    // fused gather + weight prep
    gather_kernel<<<BB + D1 + D2, 128>>>(oh_i, oh_x, mi1, mx1, mi2, mx2, ctns,
                                         wideT, deepT, w2, w3,
                                         X, wide, W2p, W3r);

    // layer 1: [B,960] x [512,960]^T -> H1[B,512] bf16
    bf16_gemm<0><<<dim3(D1 / 128, BB / 128), 256, SMEM>>>(
        X, XS, W2p, XS, b2, (void*)H1, D1, XS, nullptr, nullptr);

    // layer 2 + layer 3 (fused): [B,512] x [256,512]^T -> zp[8][B]
    bf16_gemm<1><<<dim3(D2 / 128, BB / 128), 256, SMEM>>>(
        H1, D1, W3r, D1, b3, nullptr, D2, D1, w4, zp);

    // sigmoid( sum(zp) + b4 + 32*wide )
    final_kernel<<<BB / 128, 128>>>(zp, b4, wide, out);
}

// round 17
// speedup vs baseline: 1.3565x; 1.0062x over previous
#include <cuda_runtime.h>
#include <cuda_bf16.h>
#include <math.h>
#include <stdint.h>

// ---------------- problem constants ----------------
#define BB 16384      // batch
#define FF 26         // onehot fields
#define EE 32         // embedding dim
#define LL 50         // bag length
#define D0 909
#define D1 512
#define D2 256
#define XS 960        // D0 padded (zero tail), multiple of 64

// ---------------- scratch (static device globals: allocation-free) ----------
__device__ __nv_bfloat16 g_X  [(size_t)BB * XS];   // activations bf16
__device__ __nv_bfloat16 g_W2p[(size_t)D1 * XS];   // padded w2 bf16
__device__ __nv_bfloat16 g_W3r[(size_t)D2 * D1];   // w3 bf16
__device__ __nv_bfloat16 g_H1 [(size_t)BB * D1];   // layer-1 out bf16
__device__ float         g_wide[BB];

// ---------------- helpers ----------------------------------------------------
#define CP16(dst, src) \
    asm volatile("cp.async.cg.shared.global [%0], [%1], 16;\n" :: "r"(dst), "l"(src))
#define CPCOMMIT() asm volatile("cp.async.commit_group;\n" ::)
#define CPWAIT0()  asm volatile("cp.async.wait_group 0;\n" ::)
#define CPWAIT1()  asm volatile("cp.async.wait_group 1;\n" ::)

__device__ __forceinline__ void ldsm_x4(uint32_t* r, uint32_t addr) {
    asm volatile("ldmatrix.sync.aligned.m8n8.x4.shared.b16 {%0,%1,%2,%3}, [%4];"
                 : "=r"(r[0]), "=r"(r[1]), "=r"(r[2]), "=r"(r[3]) : "r"(addr));
}

__device__ __forceinline__ void mma_bf16(float* d, const uint32_t* a, const uint32_t* b) {
    asm volatile(
        "mma.sync.aligned.m16n8k16.row.col.f32.bf16.bf16.f32 "
        "{%0,%1,%2,%3}, {%4,%5,%6,%7}, {%8,%9}, {%0,%1,%2,%3};"
        : "+f"(d[0]), "+f"(d[1]), "+f"(d[2]), "+f"(d[3])
        : "r"(a[0]), "r"(a[1]), "r"(a[2]), "r"(a[3]), "r"(b[0]), "r"(b[1]));
}

// ---------------- gather + weight prep (fused launch) ------------------------
__global__ __launch_bounds__(128) void gather_kernel(
    const int*   __restrict__ oh_i,  const float* __restrict__ oh_x,
    const int*   __restrict__ mi1,   const float* __restrict__ mx1,
    const int*   __restrict__ mi2,   const float* __restrict__ mx2,
    const float* __restrict__ ctns,
    const float* __restrict__ wideT, const float* __restrict__ deepT,
    const float* __restrict__ w2,    const float* __restrict__ w3,
    __nv_bfloat16* __restrict__ X,   float* __restrict__ wide_out,
    __nv_bfloat16* __restrict__ W2p, __nv_bfloat16* __restrict__ W3r)
{
    const int tid  = threadIdx.x;

    if (blockIdx.x >= BB) {
        int n = blockIdx.x - BB;
        if (n < D1) {
            for (int k = tid; k < XS; k += 128)
                W2p[(size_t)n * XS + k] = (k < D0) ? __float2bfloat16_rn(w2[(size_t)n * D0 + k])
                                                   : __float2bfloat16_rn(0.0f);
        } else {
            int m = n - D1;
            for (int k = tid; k < D1; k += 128)
                W3r[(size_t)m * D1 + k] = __float2bfloat16_rn(w3[(size_t)m * D1 + k]);
        }
        return;
    }

    const int row  = blockIdx.x;
    const int warp = tid >> 5;
    const int lane = tid & 31;
    __nv_bfloat16* xr = X + (size_t)row * XS;

    for (int f = warp; f < FF; f += 4) {
        int   idx = oh_i[row * FF + f];
        float w   = oh_x[row * FF + f];
        xr[f * EE + lane] = __float2bfloat16_rn(deepT[(size_t)idx * EE + lane] * w);
    }

    {
        const int*   mi = (warp < 2) ? mi1 : mi2;
        const float* mx = (warp < 2) ? mx1 : mx2;
        const int half  = warp & 1;
        float acc = 0.0f;
        for (int j = half; j < LL; j += 2) {
            int   idx = mi[row * LL + j];
            float w   = mx[row * LL + j];
            acc += deepT[(size_t)idx * EE + lane] * w;
        }
        __shared__ float sb[4][EE];
        sb[warp][lane] = acc;
        __syncthreads();
        if      (warp == 0) xr[FF * EE      + lane] = __float2bfloat16_rn(sb[0][lane] + sb[1][lane]);
        else if (warp == 1) xr[FF * EE + EE + lane] = __float2bfloat16_rn(sb[2][lane] + sb[3][lane]);
        else if (warp == 2) { if (lane < 13) xr[FF * EE + 2 * EE + lane] = __float2bfloat16_rn(ctns[row * 13 + lane]); }
    }
    if (tid < XS - D0) xr[D0 + tid] = __float2bfloat16_rn(0.0f);   // zero pad tail

    float wv = 0.0f;
    if (tid < FF) {
        wv = wideT[oh_i[row * FF + tid]] * oh_x[row * FF + tid];
    } else if (tid < FF + LL) {
        int j = tid - FF;
        wv = wideT[mi1[row * LL + j]] * mx1[row * LL + j];
    } else if (tid < FF + 2 * LL) {
        int j = tid - FF - LL;
        wv = wideT[mi2[row * LL + j]] * mx2[row * LL + j];
    }
    #pragma unroll
    for (int o = 16; o; o >>= 1) wv += __shfl_xor_sync(0xFFFFFFFFu, wv, o);
    __shared__ float swide[4];
    if (lane == 0) swide[warp] = wv;
    __syncthreads();
    if (tid == 0)
        wide_out[row] = swide[0] + swide[1] + swide[2] + swide[3];
}

// ---------------- bf16 mma.sync GEMM: C = A(M,K) * B(N,K)^T -----------------
// block 128 x BN_, BK=64, 3-stage cp.async pipeline, dynamic smem.
// NTHREADS/32 warps as 2(M) x (BN_/32)(N); warp tile 64x32; frag double-buffer.
// MODE 0 (BN_=128, 256 thr): bf16 C store (bias+leaky).
// MODE 1 (BN_=256, 512 thr): full network tail — bias+leaky, dot w4,
//   cross-warp smem reduce, +b4+32*wide, sigmoid, write out. No C.
template <int MODE, int BN_, int NTHREADS>
__global__ void __launch_bounds__(NTHREADS, NTHREADS == 256 ? 2 : 1) bf16_gemm(
    const __nv_bfloat16* __restrict__ A, int lda,
    const __nv_bfloat16* __restrict__ Bm, int ldb,
    const float* __restrict__ bias,
    void* __restrict__ Cv, int ldc, int K,
    const float* __restrict__ w4, const float* __restrict__ wide,
    const float* __restrict__ b4, float* __restrict__ out)
{
    constexpr int BM = 128, BK = 64, LDA = BK + 8;   // 72 bf16 = 144 B
    constexpr int ST = 3;
    constexpr int A_ELEMS = BM * LDA;
    constexpr int B_ELEMS = BN_ * LDA;
    constexpr int RPP = NTHREADS / 8;                // loader rows per pass

    extern __shared__ __align__(16) __nv_bfloat16 smem[];
    __nv_bfloat16* Asm = smem;
    __nv_bfloat16* Bsm = smem + ST * A_ELEMS;

    const int tid  = threadIdx.x;
    const int warp = tid >> 5;
    const int lane = tid & 31;
    const int wm = (warp & 1) * 64;        // 2 warps in M
    const int wn = (warp >> 1) * 32;       // BN_/32 warps in N
    const int r  = lane >> 2;
    const int c  = lane & 3;

    const int bm = blockIdx.y * BM;
    const int bn = blockIdx.x * BN_;

    const int lrow = tid >> 3;             // 0..RPP-1
    const int lcol = (tid & 7) * 8;        // 0..56
    const __nv_bfloat16* gA = A  + (size_t)(bm + lrow) * lda + lcol;
    const __nv_bfloat16* gB = Bm + (size_t)(bn + lrow) * ldb + lcol;

    uint32_t sAbase[ST], sBbase[ST];
    #pragma unroll
    for (int s = 0; s < ST; s++) {
        sAbase[s] = (uint32_t)__cvta_generic_to_shared(&Asm[s * A_ELEMS + lrow * LDA + lcol]);
        sBbase[s] = (uint32_t)__cvta_generic_to_shared(&Bsm[s * B_ELEMS + lrow * LDA + lcol]);
    }

    const int rowA_l = lane & 15;
    const int colA_l = (lane >> 4) << 3;
    const int rowB_l = (lane & 7) + ((lane & 16) >> 1);
    const int colB_l = lane & 8;
    uint32_t aBase[ST], bBase[ST];
    #pragma unroll
    for (int s = 0; s < ST; s++) {
        aBase[s] = (uint32_t)__cvta_generic_to_shared(
            &Asm[s * A_ELEMS + (wm + rowA_l) * LDA + colA_l]);
        bBase[s] = (uint32_t)__cvta_generic_to_shared(
            &Bsm[s * B_ELEMS + (wn + rowB_l) * LDA + colB_l]);
    }

    float acc[4][4][4];
    #pragma unroll
    for (int i = 0; i < 4; i++)
        #pragma unroll
        for (int j = 0; j < 4; j++)
            #pragma unroll
            for (int q = 0; q < 4; q++) acc[i][j][q] = 0.0f;

    const int T = K / BK;

    auto load_stage = [&](int s, int k0) {
        #pragma unroll
        for (int g = 0; g < BM / RPP; g++)
            CP16(sAbase[s] + (uint32_t)(g * RPP * LDA * 2),
                 gA + (size_t)(g * RPP) * lda + k0);
        #pragma unroll
        for (int g = 0; g < BN_ / RPP; g++)
            CP16(sBbase[s] + (uint32_t)(g * RPP * LDA * 2),
                 gB + (size_t)(g * RPP) * ldb + k0);
        CPCOMMIT();
    };

    load_stage(0, 0);
    load_stage(1, BK);

    uint32_t af[2][4][4], bq[2][2][4];

    int st = 0;
    for (int t = 0; t < T; t++) {
        if (t + 1 < T) CPWAIT1(); else CPWAIT0();
        __syncthreads();

        if (t + 2 < T) {
            int ns = st + 2; if (ns >= ST) ns -= ST;
            load_stage(ns, (t + 2) * BK);
        }

        #pragma unroll
        for (int i = 0; i < 4; i++)
            ldsm_x4(af[0][i], aBase[st] + (uint32_t)((16 * i * LDA) * 2));
        #pragma unroll
        for (int j16 = 0; j16 < 2; j16++)
            ldsm_x4(bq[0][j16], bBase[st] + (uint32_t)((16 * j16 * LDA) * 2));

        int cur = 0;
        #pragma unroll
        for (int kk = 0; kk < BK; kk += 16) {
            const int nxt = cur ^ 1;
            if (kk + 16 < BK) {
                #pragma unroll
                for (int i = 0; i < 4; i++)
                    ldsm_x4(af[nxt][i], aBase[st] + (uint32_t)((16 * i * LDA + kk + 16) * 2));
                #pragma unroll
                for (int j16 = 0; j16 < 2; j16++)
                    ldsm_x4(bq[nxt][j16], bBase[st] + (uint32_t)((16 * j16 * LDA + kk + 16) * 2));
            }
            #pragma unroll
            for (int i = 0; i < 4; i++)
                #pragma unroll
                for (int j = 0; j < 4; j++)
                    mma_bf16(acc[i][j], af[cur][i], &bq[cur][j >> 1][(j & 1) * 2]);
            cur = nxt;
        }
        if (++st == ST) st = 0;
    }

    if (MODE == 0) {
        // bias + leaky, bf16 store
        #pragma unroll
        for (int i = 0; i < 4; i++) {
            #pragma unroll
            for (int j = 0; j < 4; j++) {
                const int n0 = bn + wn + 8 * j + c * 2;
                const float bi0 = __ldg(&bias[n0]);
                const float bi1 = __ldg(&bias[n0 + 1]);
                #pragma unroll
                for (int h = 0; h < 2; h++) {
                    const int m = bm + wm + 16 * i + r + 8 * h;
                    float v0 = acc[i][j][2 * h + 0] + bi0;
                    float v1 = acc[i][j][2 * h + 1] + bi1;
                    v0 = (v0 >= 0.0f) ? v0 : 0.01f * v0;
                    v1 = (v1 >= 0.0f) ? v1 : 0.01f * v1;
                    __nv_bfloat162 o = make_bfloat162(__float2bfloat16_rn(v0),
                                                      __float2bfloat16_rn(v1));
                    *reinterpret_cast<__nv_bfloat162*>(
                        &((__nv_bfloat16*)Cv)[(size_t)m * ldc + n0]) = o;
                }
            }
        }
    } else {
        // full tail: per-warp partial dot with w4 over this warp's 32 N-cols
        float s[4][2];
        #pragma unroll
        for (int i = 0; i < 4; i++) { s[i][0] = 0.0f; s[i][1] = 0.0f; }
        #pragma unroll
        for (int j = 0; j < 4; j++) {
            const int n0 = wn + 8 * j + c * 2;
            const float bi0 = __ldg(&bias[n0]);
            const float bi1 = __ldg(&bias[n0 + 1]);
            const float w0  = __ldg(&w4[n0]);
            const float w1  = __ldg(&w4[n0 + 1]);
            #pragma unroll
            for (int i = 0; i < 4; i++)
                #pragma unroll
                for (int h = 0; h < 2; h++) {
                    float v0 = acc[i][j][2 * h + 0] + bi0;
                    float v1 = acc[i][j][2 * h + 1] + bi1;
                    v0 = (v0 >= 0.0f) ? v0 : 0.01f * v0;
                    v1 = (v1 >= 0.0f) ? v1 : 0.01f * v1;
                    s[i][h] += v0 * w0 + v1 * w1;
                }
        }
        // quad reduce across c
        #pragma unroll
        for (int i = 0; i < 4; i++)
            #pragma unroll
            for (int h = 0; h < 2; h++) {
                s[i][h] += __shfl_xor_sync(0xFFFFFFFFu, s[i][h], 1);
                s[i][h] += __shfl_xor_sync(0xFFFFFFFFu, s[i][h], 2);
            }
        // cross-warp reduce via smem (reuse tile smem; mainloop fully done)
        __syncthreads();
        float* sred = reinterpret_cast<float*>(smem);   // [128][BN_/32]
        constexpr int NW = BN_ / 32;
        if (c == 0) {
            const int p = warp >> 1;
            #pragma unroll
            for (int i = 0; i < 4; i++)
                #pragma unroll
                for (int h = 0; h < 2; h++)
                    sred[(wm + 16 * i + r + 8 * h) * NW + p] = s[i][h];
        }
        __syncthreads();
        if (tid < BM) {
            const int m = bm + tid;
            float z = __ldg(&b4[0]) + (float)EE * __ldg(&wide[m]);
            #pragma unroll
            for (int p = 0; p < NW; p++)
                z += sred[tid * NW + p];
            out[m] = 1.0f / (1.0f + expf(-z));
        }
    }
}

// ---------------- launch ----------------------------------------------------
extern "C" void kernel_launch(void* const* d_in, const int* in_sizes, int n_in,
                              void* d_out, int out_size)
{
    const int*   oh_i  = (const int*)  d_in[0];
    const float* oh_x  = (const float*)d_in[1];
    const int*   mi1   = (const int*)  d_in[2];
    const float* mx1   = (const float*)d_in[3];
    const int*   mi2   = (const int*)  d_in[4];
    const float* mx2   = (const float*)d_in[5];
    const float* ctns  = (const float*)d_in[6];
    const float* wideT = (const float*)d_in[7];
    const float* deepT = (const float*)d_in[8];
    const float* w2    = (const float*)d_in[9];
    const float* b2    = (const float*)d_in[10];
    const float* w3    = (const float*)d_in[11];
    const float* b3    = (const float*)d_in[12];
    const float* w4    = (const float*)d_in[13];
    const float* b4    = (const float*)d_in[14];
    float* out = (float*)d_out;

    __nv_bfloat16 *X, *W2p, *W3r, *H1;
    float *wide;
    cudaGetSymbolAddress((void**)&X,    g_X);
    cudaGetSymbolAddress((void**)&W2p,  g_W2p);
    cudaGetSymbolAddress((void**)&W3r,  g_W3r);
    cudaGetSymbolAddress((void**)&H1,   g_H1);
    cudaGetSymbolAddress((void**)&wide, g_wide);

    const int SMEM1 = 3 * (128 + 128) * 72 * 2;   // 110592 bytes
    const int SMEM2 = 3 * (128 + 256) * 72 * 2;   // 165888 bytes
    cudaFuncSetAttribute((const void*)bf16_gemm<0, 128, 256>,
                         cudaFuncAttributeMaxDynamicSharedMemorySize, SMEM1);
    cudaFuncSetAttribute((const void*)bf16_gemm<1, 256, 512>,
                         cudaFuncAttributeMaxDynamicSharedMemorySize, SMEM2);

    // fused gather + weight prep
    gather_kernel<<<BB + D1 + D2, 128>>>(oh_i, oh_x, mi1, mx1, mi2, mx2, ctns,
                                         wideT, deepT, w2, w3,
                                         X, wide, W2p, W3r);

    // layer 1: [B,960] x [512,960]^T -> H1[B,512] bf16
    bf16_gemm<0, 128, 256><<<dim3(D1 / 128, BB / 128), 256, SMEM1>>>(
        X, XS, W2p, XS, b2, (void*)H1, D1, XS,
        nullptr, nullptr, nullptr, nullptr);

    // layers 2+3+sigmoid fused: [B,512] x [256,512]^T -> out[B]
    bf16_gemm<1, 256, 512><<<dim3(1, BB / 128), 512, SMEM2>>>(
        H1, D1, W3r, D1, b3, nullptr, D2, D1,
        w4, wide, b4, out);
}